// round 3
// baseline (speedup 1.0000x reference)
#include <cuda_runtime.h>

// Problem constants (fixed by the reference)
#define NB        2000                  // N_BUSES
#define BATCH     32                    // B
#define NEDGE     6000                  // E per batch
#define TOT_NODES (BATCH * NB)          // 64000
#define TOT_EDGES (BATCH * NEDGE)       // 192000
#define HSLOTS    8192                  // per-batch smem hash slots (pow2, load 0.73)
#define HMASK     (HSLOTS - 1)
#define NTHR      1024

// Per-block partial sums: d1r, d1i, d2, d3, mse  (overwritten every call -> no init kernel)
__device__ double g_part[BATCH][5];

// Dynamic smem layout:
//   [0,      65536)  hash:  8192 x u64   ((cell+1)<<32 | edge_id)
//   [65536,  81920)  V:     2048 x float2 (outs for this batch; 2000 used)
//   [81920,  97920)  YV:    2000 x float2
#define SMEM_BYTES (HSLOTS * 8 + 2048 * 8 + 2000 * 8)

__device__ __forceinline__ unsigned hash_cell(unsigned cell) {
    // multiplicative hash, take high bits (cell fits in 22 bits)
    return (cell * 2654435761u) >> (32 - 13);   // 13 = log2(HSLOTS)
}

__global__ __launch_bounds__(NTHR, 1)
void k_fused(const float* __restrict__ x,
             const float* __restrict__ ea,
             const int*   __restrict__ ei,
             const float* __restrict__ outs,
             const float* __restrict__ labels) {
    extern __shared__ char smem[];
    unsigned long long* hash = (unsigned long long*)smem;
    float2* V  = (float2*)(smem + HSLOTS * 8);
    float2* YV = V + 2048;

    const int b   = blockIdx.x;          // one block == one batch
    const int tid = threadIdx.x;
    const float2* outs2 = (const float2*)outs;

    // ---- clear hash + YV, stage V into smem ----
    #pragma unroll
    for (int s = tid; s < HSLOTS; s += NTHR) hash[s] = 0ULL;
    for (int n = tid; n < NB; n += NTHR) {
        YV[n] = make_float2(0.f, 0.f);
        V[n]  = outs2[b * NB + n];
    }
    __syncthreads();

    // ---- pass 1: last-write-wins insert (JAX .set semantics: max edge id wins) ----
    for (int e = tid; e < NEDGE; e += NTHR) {
        int t = b * NEDGE + e;
        int i = ei[t] % NB;              if (i < 0) i += NB;
        int j = ei[TOT_EDGES + t] % NB;  if (j < 0) j += NB;
        unsigned cell = (unsigned)(i * NB + j) + 1u;         // +1: 0 == empty
        unsigned long long mine = ((unsigned long long)cell << 32) | (unsigned)e;
        unsigned h = hash_cell(cell);
        while (true) {
            unsigned long long old = atomicCAS(&hash[h], 0ULL, mine);
            if (old == 0ULL) break;
            if ((unsigned)(old >> 32) == cell) { atomicMax(&hash[h], mine); break; }
            h = (h + 1) & HMASK;
        }
    }
    __syncthreads();

    // ---- pass 2: scan slots, scatter adm*V[j] into YV[i] (unique cells only) ----
    for (int s = tid; s < HSLOTS; s += NTHR) {
        unsigned long long ent = hash[s];
        if (ent == 0ULL) continue;
        unsigned cell = (unsigned)(ent >> 32) - 1u;
        int e = (int)(unsigned)ent;
        int i = (int)(cell / NB);
        int j = (int)(cell - (unsigned)i * NB);
        int t = b * NEDGE + e;
        float ar = ea[2 * t], ai = ea[2 * t + 1];
        float2 v = V[j];
        atomicAdd(&YV[i].x, ar * v.x - ai * v.y);
        atomicAdd(&YV[i].y, ar * v.y + ai * v.x);
    }
    __syncthreads();

    // ---- pass 3: per-node physics + MSE terms ----
    double a0 = 0, a1 = 0, a2 = 0, a3 = 0, a4 = 0;
    for (int n = tid; n < NB; n += NTHR) {
        int idx = b * NB + n;
        float2 v  = V[n];
        float2 yv = YV[n];
        // Spred = V * conj(YV)
        float spr = v.x * yv.x + v.y * yv.y;
        float spi = v.y * yv.x - v.x * yv.y;

        const float2* nf2 = (const float2*)(x + 6 * idx);
        float2 p0 = nf2[0], p1 = nf2[1], p2 = nf2[2];
        float sr = p0.x, si = p0.y, Vm = p1.x;
        float b0 = p1.y, b1 = p2.x, b2 = p2.y;

        float dr = spr - sr;
        float di = spi - si;
        float sinv = rsqrtf(sr * sr + si * si);              // |1/S|

        a0 += (double)(sinv * ((dr * dr - di * di) * b0 + dr * dr * b1));
        a1 += (double)(sinv * (2.f * dr * di * b0));

        float vmag  = sqrtf(v.x * v.x + v.y * v.y);
        float vminv = 1.f / Vm;
        a2 += (double)(fabsf(vmag * (b1 + b2) - Vm) * vminv);
        a3 += (double)(fabsf(v.y * b2) * vminv);

        const float2 lab = ((const float2*)labels)[idx];
        float e0 = v.x - lab.x;
        float e1 = v.y - lab.y;
        a4 += (double)(e0 * e0) + (double)(e1 * e1);
    }

    // ---- block reduction (32 warps) ----
    #pragma unroll
    for (int o = 16; o > 0; o >>= 1) {
        a0 += __shfl_down_sync(0xFFFFFFFFu, a0, o);
        a1 += __shfl_down_sync(0xFFFFFFFFu, a1, o);
        a2 += __shfl_down_sync(0xFFFFFFFFu, a2, o);
        a3 += __shfl_down_sync(0xFFFFFFFFu, a3, o);
        a4 += __shfl_down_sync(0xFFFFFFFFu, a4, o);
    }
    __syncthreads();                                         // smem reuse below
    double* red = (double*)smem;                             // 5 x 32 doubles
    int lane = tid & 31, warp = tid >> 5;
    if (lane == 0) {
        red[0 * 32 + warp] = a0; red[1 * 32 + warp] = a1; red[2 * 32 + warp] = a2;
        red[3 * 32 + warp] = a3; red[4 * 32 + warp] = a4;
    }
    __syncthreads();
    if (warp == 0) {
        double v0 = red[0 * 32 + lane];
        double v1 = red[1 * 32 + lane];
        double v2 = red[2 * 32 + lane];
        double v3 = red[3 * 32 + lane];
        double v4 = red[4 * 32 + lane];
        #pragma unroll
        for (int o = 16; o > 0; o >>= 1) {
            v0 += __shfl_down_sync(0xFFFFFFFFu, v0, o);
            v1 += __shfl_down_sync(0xFFFFFFFFu, v1, o);
            v2 += __shfl_down_sync(0xFFFFFFFFu, v2, o);
            v3 += __shfl_down_sync(0xFFFFFFFFu, v3, o);
            v4 += __shfl_down_sync(0xFFFFFFFFu, v4, o);
        }
        if (lane == 0) {
            g_part[b][0] = v0; g_part[b][1] = v1; g_part[b][2] = v2;
            g_part[b][3] = v3; g_part[b][4] = v4;
        }
    }
}

// ------------------------------------------------------------------ finalize
// Output: 5 float32 = real parts of (loss, physics_loss, d1, d2, d3).
__global__ void k_final(float* __restrict__ out, int nfloats) {
    int lane = threadIdx.x;                                  // 32 threads
    double v0 = g_part[lane][0], v1 = g_part[lane][1], v2 = g_part[lane][2],
           v3 = g_part[lane][3], v4 = g_part[lane][4];
    #pragma unroll
    for (int o = 16; o > 0; o >>= 1) {
        v0 += __shfl_down_sync(0xFFFFFFFFu, v0, o);
        v1 += __shfl_down_sync(0xFFFFFFFFu, v1, o);
        v2 += __shfl_down_sync(0xFFFFFFFFu, v2, o);
        v3 += __shfl_down_sync(0xFFFFFFFFu, v3, o);
        v4 += __shfl_down_sync(0xFFFFFFFFu, v4, o);
    }
    if (lane == 0) {
        const double inv = 1.0 / (double)TOT_NODES;
        double d1r = v0 * inv;
        double d1i = v1 * inv;
        double d2  = v2 * inv;
        double d3  = v3 * inv;
        double mse = v4 / (double)(TOT_NODES * 2);
        double pr  = d1r + d2 + d3;
        double pi  = d1i;
        double lr  = mse + 0.1 * pr;
        double li  = 0.1 * pi;
        float vals[10] = { (float)lr, (float)pr, (float)d1r, (float)d2, (float)d3,
                           (float)li, (float)pi, (float)d1i, 0.f, 0.f };
        for (int k = 0; k < nfloats && k < 10; k++) out[k] = vals[k];
    }
}

// ------------------------------------------------------------------ launcher
extern "C" void kernel_launch(void* const* d_in, const int* in_sizes, int n_in,
                              void* d_out, int out_size) {
    const float* x      = (const float*)d_in[0];   // (B*2000, 6)
    const float* ea     = (const float*)d_in[1];   // (B*6000, 2)
    const int*   ei     = (const int*)  d_in[2];   // (2, B*6000)
    const float* outs   = (const float*)d_in[3];   // (B*2000, 2)
    const float* labels = (const float*)d_in[4];   // (B*2000, 2)
    (void)in_sizes; (void)n_in;

    int nfloats = out_size < 10 ? out_size : 10;

    cudaFuncSetAttribute(k_fused, cudaFuncAttributeMaxDynamicSharedMemorySize,
                         SMEM_BYTES);

    k_fused <<<BATCH, NTHR, SMEM_BYTES>>>(x, ea, ei, outs, labels);
    k_final <<<1, 32>>>((float*)d_out, nfloats);
}